// round 1
// baseline (speedup 1.0000x reference)
#include <cuda_runtime.h>

// SphArr: complex orthonormal spherical harmonics Y_l^m, l<4, over 524288 points.
// Out layout per point: 16 (l,m)-components x (re,im) = 32 contiguous floats.
// Strategy: 1 thread = 1 point; stage block output in padded SMEM; coalesced
// float4 global stores. HBM-write-bound (~70 MB traffic).

#define PTS_PER_BLOCK 256
#define NBLOCKS ((8 * 256 * 256) / PTS_PER_BLOCK)

__global__ __launch_bounds__(256) void sph_kernel(const float* __restrict__ X,
                                                  float4* __restrict__ out) {
    // 9 float4 per point (8 used + 1 pad) -> conflict-free smem on both sides.
    __shared__ float4 sm[PTS_PER_BLOCK * 9];

    const int tid = threadIdx.x;
    const unsigned p = blockIdx.x * (unsigned)PTS_PER_BLOCK + tid;

    const float x = X[3u * p + 0];
    const float y = X[3u * p + 1];
    const float z = X[3u * p + 2];

    const float rho2 = fmaf(x, x, y * y);
    const float r2   = fmaf(z, z, rho2);
    const float rinv = rsqrtf(r2);
    const float ct   = z * rinv;                 // cos(theta)
    const float st   = sqrtf(rho2) * rinv;       // sin(theta) >= 0 (== sqrt(clip(1-ct^2)))

    // cos/sin of phi = atan2(y, x), and of 2phi, 3phi via doubling.
    const bool  ok     = rho2 > 0.0f;
    const float rhoinv = ok ? rsqrtf(rho2) : 0.0f;
    const float c1 = ok ? x * rhoinv : 1.0f;
    const float s1 = y * rhoinv;                 // 0 when rho2==0
    const float c2 = c1 * c1 - s1 * s1;
    const float s2 = 2.0f * c1 * s1;
    const float c3 = c1 * c2 - s1 * s2;
    const float s3 = s1 * c2 + c1 * s2;

    const float ct2 = ct * ct;
    const float st2 = st * st;

    // Associated Legendre with Condon-Shortley phase (matches reference recurrence):
    // P11 = -st; P21 = -3 ct st; P22 = 3 st^2
    // P31 = -1.5 st (5ct^2-1); P32 = 15 ct st^2; P33 = -15 st^3
    const float b11 = 0.34549414947133547f * (-st);
    const float re1 = b11 * c1, im1 = b11 * s1;

    const float b21 = 0.25751613468215834f * (-3.0f * ct * st);
    const float re21 = b21 * c1, im21 = b21 * s1;
    const float b22 = 0.12875806734107764f * (3.0f * st2);
    const float re22 = b22 * c2, im22 = b22 * s2;

    const float b31 = 0.21545345607610053f * (-1.5f * st * (5.0f * ct2 - 1.0f));
    const float re31 = b31 * c1, im31 = b31 * s1;
    const float b32 = 0.06813236509755226f * (15.0f * ct * st2);
    const float re32 = b32 * c2, im32 = b32 * s2;
    const float b33 = 0.027814921575518937f * (-15.0f * st2 * st);
    const float re33 = b33 * c3, im33 = b33 * s3;

    float v[32];
    // l=0
    v[0]  = 0.28209479177387814f;                      v[1]  = 0.0f;
    // l=1: m=-1,0,1   (Y_l^{-m} = (-1)^m conj(Y_l^m))
    v[2]  = -re1;                                      v[3]  = im1;
    v[4]  = 0.48860251190291992f * ct;                 v[5]  = 0.0f;
    v[6]  = re1;                                       v[7]  = im1;
    // l=2: m=-2..2
    v[8]  = re22;                                      v[9]  = -im22;
    v[10] = -re21;                                     v[11] = im21;
    v[12] = 0.63078313050504009f * 0.5f * (3.0f * ct2 - 1.0f); v[13] = 0.0f;
    v[14] = re21;                                      v[15] = im21;
    v[16] = re22;                                      v[17] = im22;
    // l=3: m=-3..3
    v[18] = -re33;                                     v[19] = im33;
    v[20] = re32;                                      v[21] = -im32;
    v[22] = -re31;                                     v[23] = im31;
    v[24] = 0.74635266518023113f * 0.5f * ct * (5.0f * ct2 - 3.0f); v[25] = 0.0f;
    v[26] = re31;                                      v[27] = im31;
    v[28] = re32;                                      v[29] = im32;
    v[30] = re33;                                      v[31] = im33;

#pragma unroll
    for (int q = 0; q < 8; q++)
        sm[tid * 9 + q] = make_float4(v[4 * q], v[4 * q + 1], v[4 * q + 2], v[4 * q + 3]);

    __syncthreads();

    // Coalesced stream-out: 2048 float4 per block, consecutive addresses.
    float4* dst = out + (unsigned long long)blockIdx.x * (PTS_PER_BLOCK * 8ull);
#pragma unroll
    for (int i = 0; i < 8; i++) {
        const int idx = tid + i * 256;
        dst[idx] = sm[(idx >> 3) * 9 + (idx & 7)];
    }
}

extern "C" void kernel_launch(void* const* d_in, const int* in_sizes, int n_in,
                              void* d_out, int out_size) {
    const float* X = (const float*)d_in[0];
    float4* out = (float4*)d_out;
    sph_kernel<<<NBLOCKS, 256>>>(X, out);
}

// round 3
// speedup vs baseline: 1.0021x; 1.0021x over previous
#include <cuda_runtime.h>
#include <cuda.h>
#include <cstdint>

// SphArr: complex orthonormal spherical harmonics Y_l^m, l<4, over 524288 points.
// Out per point: 16 (l,m) x (re,im) = 32 contiguous floats (128B).
// Fast path: 1 thread = 1 point; SW128-swizzled SMEM staging (32KB/block) + one
// TMA tensor store per block (HW unswizzle, bypasses L1 store path).
// Fallback (if driver entrypoint/tensormap unavailable): padded-SMEM + coalesced
// float4 STG (the proven 15.1us R1 kernel). No crash possible in kernel_launch.

#define PTS_PER_BLOCK 256
#define NPOINTS (8 * 256 * 256)
#define NBLOCKS (NPOINTS / PTS_PER_BLOCK)

// ---- shared math: computes the 8 float4 components of one point's output row ----
__device__ __forceinline__ void sph_point(const float* __restrict__ X, unsigned p,
                                          float4 v[8]) {
    const float x = X[3u * p + 0];
    const float y = X[3u * p + 1];
    const float z = X[3u * p + 2];

    const float rho2 = fmaf(x, x, y * y);
    const float r2   = fmaf(z, z, rho2);
    const float rinv = rsqrtf(r2);
    const float ct   = z * rinv;                 // cos(theta)
    const float st   = sqrtf(rho2) * rinv;       // sin(theta) >= 0

    const bool  ok     = rho2 > 0.0f;
    const float rhoinv = ok ? rsqrtf(rho2) : 0.0f;
    const float c1 = ok ? x * rhoinv : 1.0f;
    const float s1 = y * rhoinv;
    const float c2 = c1 * c1 - s1 * s1;
    const float s2 = 2.0f * c1 * s1;
    const float c3 = c1 * c2 - s1 * s2;
    const float s3 = s1 * c2 + c1 * s2;

    const float ct2 = ct * ct;
    const float st2 = st * st;

    // Associated Legendre w/ Condon-Shortley phase (matches reference recurrence).
    const float b11 = 0.34549414947133547f * (-st);
    const float re1 = b11 * c1, im1 = b11 * s1;

    const float b21 = 0.25751613468215834f * (-3.0f * ct * st);
    const float re21 = b21 * c1, im21 = b21 * s1;
    const float b22 = 0.12875806734107764f * (3.0f * st2);
    const float re22 = b22 * c2, im22 = b22 * s2;

    const float b31 = 0.21545345607610053f * (-1.5f * st * (5.0f * ct2 - 1.0f));
    const float re31 = b31 * c1, im31 = b31 * s1;
    const float b32 = 0.06813236509755226f * (15.0f * ct * st2);
    const float re32 = b32 * c2, im32 = b32 * s2;
    const float b33 = 0.027814921575518937f * (-15.0f * st2 * st);
    const float re33 = b33 * c3, im33 = b33 * s3;

    const float y00 = 0.28209479177387814f;
    const float y10 = 0.48860251190291992f * ct;
    const float y20 = 0.63078313050504009f * 0.5f * (3.0f * ct2 - 1.0f);
    const float y30 = 0.74635266518023113f * 0.5f * ct * (5.0f * ct2 - 3.0f);

    v[0] = make_float4(y00, 0.0f, -re1, im1);
    v[1] = make_float4(y10, 0.0f, re1, im1);
    v[2] = make_float4(re22, -im22, -re21, im21);
    v[3] = make_float4(y20, 0.0f, re21, im21);
    v[4] = make_float4(re22, im22, -re33, im33);
    v[5] = make_float4(re32, -im32, -re31, im31);
    v[6] = make_float4(y30, 0.0f, re31, im31);
    v[7] = make_float4(re32, im32, re33, im33);
}

// ---- fast path: SW128 smem + TMA tensor store ----
__global__ __launch_bounds__(256) void sph_kernel_tma(
    const __grid_constant__ CUtensorMap tmap,
    const float* __restrict__ X) {
    __shared__ __align__(1024) float4 sm[PTS_PER_BLOCK * 8];  // 32KB, SW128 layout

    const int tid = threadIdx.x;
    const unsigned p = blockIdx.x * (unsigned)PTS_PER_BLOCK + tid;

    float4 v[8];
    sph_point(X, p, v);

    // SW128: float4 slot c of row tid lands at slot c ^ (tid & 7).
    // Per 8-lane phase all 8 banks-groups distinct -> conflict-free STS.128.
    float4* row = sm + tid * 8;
    const int rot = tid & 7;
    row[0 ^ rot] = v[0];
    row[1 ^ rot] = v[1];
    row[2 ^ rot] = v[2];
    row[3 ^ rot] = v[3];
    row[4 ^ rot] = v[4];
    row[5 ^ rot] = v[5];
    row[6 ^ rot] = v[6];
    row[7 ^ rot] = v[7];

    __syncthreads();

    if (tid == 0) {
        uint32_t saddr;
        asm("{ .reg .u64 t; cvta.to.shared.u64 t, %1; cvt.u32.u64 %0, t; }"
            : "=r"(saddr) : "l"((const void*)sm));
        const int row0 = blockIdx.x * PTS_PER_BLOCK;
        asm volatile("fence.proxy.async;" ::: "memory");
        asm volatile(
            "cp.async.bulk.tensor.2d.global.shared::cta.tile.bulk_group "
            "[%0, {%1, %2}], [%3];"
            :: "l"(&tmap), "r"(0), "r"(row0), "r"(saddr)
            : "memory");
        asm volatile("cp.async.bulk.commit_group;" ::: "memory");
        asm volatile("cp.async.bulk.wait_group.read 0;" ::: "memory");
    }
}

// ---- fallback path: padded smem + coalesced float4 STG (proven R1 kernel) ----
__global__ __launch_bounds__(256) void sph_kernel_stg(const float* __restrict__ X,
                                                      float4* __restrict__ out) {
    __shared__ float4 sm[PTS_PER_BLOCK * 9];  // +1 float4/row pad: conflict-free

    const int tid = threadIdx.x;
    const unsigned p = blockIdx.x * (unsigned)PTS_PER_BLOCK + tid;

    float4 v[8];
    sph_point(X, p, v);

#pragma unroll
    for (int q = 0; q < 8; q++) sm[tid * 9 + q] = v[q];

    __syncthreads();

    float4* dst = out + (unsigned long long)blockIdx.x * (PTS_PER_BLOCK * 8ull);
#pragma unroll
    for (int i = 0; i < 8; i++) {
        const int idx = tid + i * 256;
        dst[idx] = sm[(idx >> 3) * 9 + (idx & 7)];
    }
}

typedef CUresult (*EncodeFn)(
    CUtensorMap*, CUtensorMapDataType, cuuint32_t, void*,
    const cuuint64_t*, const cuuint64_t*, const cuuint32_t*, const cuuint32_t*,
    CUtensorMapInterleave, CUtensorMapSwizzle, CUtensorMapL2promotion,
    CUtensorMapFloatOOBfill);

extern "C" void kernel_launch(void* const* d_in, const int* in_sizes, int n_in,
                              void* d_out, int out_size) {
    const float* X = (const float*)d_in[0];

    // Resolve cuTensorMapEncodeTiled via the runtime, with full validation.
    void* fn = nullptr;
    cudaDriverEntryPointQueryResult qst = cudaDriverEntryPointSymbolNotFound;
    cudaError_t qerr = cudaGetDriverEntryPointByVersion(
        "cuTensorMapEncodeTiled", &fn, 12000, cudaEnableDefault, &qst);

    bool tma_ok = false;
    CUtensorMap tmap;
    if (qerr == cudaSuccess && qst == cudaDriverEntryPointSuccess && fn != nullptr) {
        EncodeFn encode = (EncodeFn)fn;
        cuuint64_t dims[2]    = {32, (cuuint64_t)NPOINTS};  // 32 f32 per row
        cuuint64_t strides[1] = {128};                      // 128B row stride
        cuuint32_t box[2]     = {32, PTS_PER_BLOCK};        // 128B x 256 = 32KB
        cuuint32_t estr[2]    = {1, 1};
        CUresult r = encode(&tmap, CU_TENSOR_MAP_DATA_TYPE_FLOAT32, 2, d_out,
                            dims, strides, box, estr,
                            CU_TENSOR_MAP_INTERLEAVE_NONE,
                            CU_TENSOR_MAP_SWIZZLE_128B,
                            CU_TENSOR_MAP_L2_PROMOTION_L2_128B,
                            CU_TENSOR_MAP_FLOAT_OOB_FILL_NONE);
        tma_ok = (r == CUDA_SUCCESS);
    }

    if (tma_ok) {
        sph_kernel_tma<<<NBLOCKS, PTS_PER_BLOCK>>>(tmap, X);
    } else {
        sph_kernel_stg<<<NBLOCKS, PTS_PER_BLOCK>>>(X, (float4*)d_out);
    }
}